// round 3
// baseline (speedup 1.0000x reference)
#include <cuda_runtime.h>
#include <stdint.h>
#include <math_constants.h>

// ProbSparse attention (Informer) — B=4, L=2048, H=8, D=64, U_part=u=40.
// Layout of all tensors: (B, L, H, D) row-major.

#define BB 4
#define LL 2048
#define HH 8
#define DD 64
#define UU 40            // top-u queries
#define SS 40            // samples per query
#define BH (BB*HH)       // 32
#define NEL (LL*SS)      // 81920 sampled indices
#define NCH 16           // key chunks for split-K attention
#define CH  128          // keys per chunk
#define SCALE 0.125f     // 1/sqrt(64)

__device__ __align__(16) int   g_idx[NEL];
__device__ __align__(16) float g_M[BH*LL];
__device__ __align__(16) int   g_Mtop[BH*UU];
__device__ __align__(16) float g_Vmean[BH*DD];
__device__ __align__(16) float g_pm[BH*UU*NCH];
__device__ __align__(16) float g_ps[BH*UU*NCH];
__device__ __align__(16) float g_pa[BH*UU*NCH*DD];

// ---------------------------------------------------------------------------
// Threefry-2x32-20, constexpr-evaluable (for deriving the split key at
// compile time) and reused in the device RNG kernel.
// ---------------------------------------------------------------------------
__host__ __device__ constexpr uint64_t tf2x32(uint32_t k0, uint32_t k1,
                                              uint32_t c0, uint32_t c1) {
    uint32_t ks0 = k0, ks1 = k1, ks2 = k0 ^ k1 ^ 0x1BD11BDAu;
    uint32_t x0 = c0 + ks0, x1 = c1 + ks1;
    const int rotA[4] = {13, 15, 26, 6};
    const int rotB[4] = {17, 29, 16, 24};
    for (int g = 0; g < 5; g++) {
        const int* rot = (g & 1) ? rotB : rotA;
        for (int r = 0; r < 4; r++) {
            x0 += x1;
            x1 = (x1 << rot[r]) | (x1 >> (32 - rot[r]));
            x1 ^= x0;
        }
        uint32_t inj0 = 0, inj1 = 0;
        switch (g) {
            case 0: inj0 = ks1; inj1 = ks2 + 1u; break;
            case 1: inj0 = ks2; inj1 = ks0 + 2u; break;
            case 2: inj0 = ks0; inj1 = ks1 + 3u; break;
            case 3: inj0 = ks1; inj1 = ks2 + 4u; break;
            case 4: inj0 = ks2; inj1 = ks0 + 5u; break;
        }
        x0 += inj0; x1 += inj1;
    }
    return ((uint64_t)x0 << 32) | (uint64_t)x1;
}

// k2 = second output key of jax.random.split(key(42), 2) in partitionable
// (fold-like) mode: full threefry pair of key (0,42) at counter (hi=0, lo=1).
constexpr uint64_t K2PAIR = tf2x32(0u, 42u, 0u, 1u);
#define K2_HI ((uint32_t)(K2PAIR >> 32))
#define K2_LO ((uint32_t)(K2PAIR & 0xffffffffu))

// ---------------------------------------------------------------------------
// K1: jax.random.randint(key(42), (2048,40), 0, 2048), jax_threefry_partitionable:
//   k1,k2 = split(key); span=2048 is 2^11 -> multiplier term = 0 ->
//   result = random_bits(k2) & 2047, where random_bits(k2)[i] = fold-xor of
//   threefry2x32(k2, (0, i)).
// ---------------------------------------------------------------------------
__global__ void k_rng() {
    int i = blockIdx.x * blockDim.x + threadIdx.x;
    if (i >= NEL) return;
    uint64_t y = tf2x32(K2_HI, K2_LO, 0u, (uint32_t)i);
    uint32_t bits = (uint32_t)(y >> 32) ^ (uint32_t)(y & 0xffffffffu);
    g_idx[i] = (int)(bits & (LL - 1));
}

// ---------------------------------------------------------------------------
// K2: M[b,h,l] = max_s(q·k_sample) - sum_s(q·k_sample)/L.  One warp per (b,h,l).
// ---------------------------------------------------------------------------
__global__ void k_sampleM(const float* __restrict__ Q, const float* __restrict__ K) {
    int wg   = (blockIdx.x * blockDim.x + threadIdx.x) >> 5;
    int lane = threadIdx.x & 31;
    if (wg >= BH * LL) return;
    int l  = wg & (LL - 1);
    int bh = wg >> 11;           // b*H + h
    int h  = bh & (HH - 1);
    int b  = bh >> 3;

    const float* qp = Q + (((size_t)(b * LL + l)) * HH + h) * DD;
    float q0 = qp[lane], q1 = qp[lane + 32];

    float mx = -CUDART_INF_F, sm = 0.f;
    const int* idx = g_idx + l * SS;
#pragma unroll 8
    for (int s = 0; s < SS; s++) {
        int kk = idx[s];
        const float* kp = K + (((size_t)(b * LL + kk)) * HH + h) * DD;
        float p = q0 * kp[lane] + q1 * kp[lane + 32];
        p += __shfl_xor_sync(0xffffffffu, p, 16);
        p += __shfl_xor_sync(0xffffffffu, p, 8);
        p += __shfl_xor_sync(0xffffffffu, p, 4);
        p += __shfl_xor_sync(0xffffffffu, p, 2);
        p += __shfl_xor_sync(0xffffffffu, p, 1);
        mx = fmaxf(mx, p);
        sm += p;
    }
    if (lane == 0) g_M[wg] = mx - sm * (1.0f / (float)LL);
}

// ---------------------------------------------------------------------------
// K3: top-40 of M per (b,h); jax.lax.top_k tie-break = lower index first.
// ---------------------------------------------------------------------------
__global__ void k_topk() {
    int bh = blockIdx.x;
    __shared__ float sv[LL];
    __shared__ float rv[256];
    __shared__ int   ri[256];
    int t = threadIdx.x;
    for (int i = t; i < LL; i += 256) sv[i] = g_M[bh * LL + i];
    __syncthreads();
    for (int it = 0; it < UU; it++) {
        float bestv = -CUDART_INF_F;
        int   besti = LL;
        for (int i = t; i < LL; i += 256) {
            float v = sv[i];
            if (v > bestv) { bestv = v; besti = i; }
        }
        rv[t] = bestv; ri[t] = besti;
        __syncthreads();
        for (int off = 128; off > 0; off >>= 1) {
            if (t < off) {
                float v2 = rv[t + off]; int i2 = ri[t + off];
                if (v2 > rv[t] || (v2 == rv[t] && i2 < ri[t])) { rv[t] = v2; ri[t] = i2; }
            }
            __syncthreads();
        }
        if (t == 0) { g_Mtop[bh * UU + it] = ri[0]; sv[ri[0]] = -CUDART_INF_F; }
        __syncthreads();
    }
}

// ---------------------------------------------------------------------------
// K4: V_mean[b,h,d] = mean over L of V[b,l,h,d].
// ---------------------------------------------------------------------------
__global__ void k_vmean(const float* __restrict__ V) {
    int bh = blockIdx.x;
    int b = bh >> 3, h = bh & 7;
    int t = threadIdx.x;
    int d = t & 63, part = t >> 6;
    float s = 0.f;
    int l0 = part * (LL / 4);
    for (int l = l0; l < l0 + (LL / 4); l++)
        s += V[(((size_t)(b * LL + l)) * HH + h) * DD + d];
    __shared__ float red[256];
    red[t] = s;
    __syncthreads();
    if (t < 128) red[t] += red[t + 128];
    __syncthreads();
    if (t < 64) {
        float tot = red[t] + red[t + 64];
        g_Vmean[bh * DD + t] = tot * (1.0f / (float)LL);
    }
}

// ---------------------------------------------------------------------------
// K5: out[b,l,h,:] = V_mean[b,h,:] for all l.
// ---------------------------------------------------------------------------
__global__ void k_fill(float* __restrict__ out) {
    int i = blockIdx.x * blockDim.x + threadIdx.x;
    if (i >= BB * LL * HH * (DD / 4)) return;
    int q4  = i & 15;
    int row = i >> 4;
    int h = row & 7;
    int b = row >> 14;
    float4 vm = reinterpret_cast<const float4*>(g_Vmean)[((b << 3) + h) * (DD / 4) + q4];
    reinterpret_cast<float4*>(out)[i] = vm;
}

// ---------------------------------------------------------------------------
// K6a: split-K attention partials. Block = (b,h, key-chunk of 128), 256 thr.
// ---------------------------------------------------------------------------
#define QS_PITCH 65
#define KS_PITCH 65
#define S_PITCH  129
#define SH_FLOATS (UU*QS_PITCH + CH*KS_PITCH + CH*KS_PITCH + UU*S_PITCH)
#define SH_BYTES  (SH_FLOATS*4 + UU*4)

__global__ void k_attn_part(const float* __restrict__ Q, const float* __restrict__ K,
                            const float* __restrict__ V) {
    int ch = blockIdx.x & (NCH - 1);
    int bh = blockIdx.x >> 4;
    int b = bh >> 3, h = bh & 7;
    int t = threadIdx.x;

    extern __shared__ float sh[];
    float* Qs = sh;                          // [40][65]
    float* Ks = Qs + UU * QS_PITCH;          // [128][65]
    float* Vs = Ks + CH * KS_PITCH;          // [128][65]
    float* S  = Vs + CH * KS_PITCH;          // [40][129]
    int* sidx = (int*)(S + UU * S_PITCH);    // [40]

    if (t < UU) sidx[t] = g_Mtop[bh * UU + t];
    __syncthreads();

    for (int i = t; i < UU * DD; i += 256) {
        int j = i >> 6, d = i & 63;
        Qs[j * QS_PITCH + d] = Q[(((size_t)(b * LL + sidx[j])) * HH + h) * DD + d];
    }
    int k0 = ch * CH;
    for (int i = t; i < CH * DD; i += 256) {
        int r = i >> 6, d = i & 63;
        size_t base = (((size_t)(b * LL + k0 + r)) * HH + h) * DD + d;
        Ks[r * KS_PITCH + d] = K[base];
        Vs[r * KS_PITCH + d] = V[base];
    }
    __syncthreads();

    // ---- phase 1: S[j][k] = scale * dot(Qs[j], Ks[k]) ----
    {
        int kg = t & 31, jg = t >> 5;
        float acc[5][4];
#pragma unroll
        for (int jt = 0; jt < 5; jt++)
#pragma unroll
            for (int kt = 0; kt < 4; kt++) acc[jt][kt] = 0.f;
#pragma unroll 8
        for (int d = 0; d < DD; d++) {
            float qv[5], kv[4];
#pragma unroll
            for (int jt = 0; jt < 5; jt++) qv[jt] = Qs[(jg + 8 * jt) * QS_PITCH + d];
#pragma unroll
            for (int kt = 0; kt < 4; kt++) kv[kt] = Ks[(kg + 32 * kt) * KS_PITCH + d];
#pragma unroll
            for (int jt = 0; jt < 5; jt++)
#pragma unroll
                for (int kt = 0; kt < 4; kt++) acc[jt][kt] += qv[jt] * kv[kt];
        }
#pragma unroll
        for (int jt = 0; jt < 5; jt++)
#pragma unroll
            for (int kt = 0; kt < 4; kt++)
                S[(jg + 8 * jt) * S_PITCH + (kg + 32 * kt)] = acc[jt][kt] * SCALE;
    }
    __syncthreads();

    // ---- phase 2: per-row chunk softmax stats; S <- exp(S - m) ----
    {
        int lane = t & 31, w = t >> 5;
#pragma unroll
        for (int i = 0; i < 5; i++) {
            int j = w * 5 + i;
            float* row = S + j * S_PITCH;
            float v0 = row[lane], v1 = row[lane + 32], v2 = row[lane + 64], v3 = row[lane + 96];
            float m = fmaxf(fmaxf(v0, v1), fmaxf(v2, v3));
            for (int off = 16; off; off >>= 1) m = fmaxf(m, __shfl_xor_sync(0xffffffffu, m, off));
            float e0 = expf(v0 - m), e1 = expf(v1 - m), e2 = expf(v2 - m), e3 = expf(v3 - m);
            row[lane] = e0; row[lane + 32] = e1; row[lane + 64] = e2; row[lane + 96] = e3;
            float s = e0 + e1 + e2 + e3;
            for (int off = 16; off; off >>= 1) s += __shfl_xor_sync(0xffffffffu, s, off);
            if (lane == 0) {
                g_pm[(bh * UU + j) * NCH + ch] = m;
                g_ps[(bh * UU + j) * NCH + ch] = s;
            }
        }
    }
    __syncthreads();

    // ---- phase 3: partial a[j][d] = sum_k exp * Vs[k][d] ----
    {
        int d = t & 63, grp = t >> 6;
        float a[10];
#pragma unroll
        for (int jt = 0; jt < 10; jt++) a[jt] = 0.f;
#pragma unroll 4
        for (int k = 0; k < CH; k++) {
            float vv = Vs[k * KS_PITCH + d];
#pragma unroll
            for (int jt = 0; jt < 10; jt++) a[jt] += S[(grp * 10 + jt) * S_PITCH + k] * vv;
        }
#pragma unroll
        for (int jt = 0; jt < 10; jt++)
            g_pa[((bh * UU + grp * 10 + jt) * NCH + ch) * DD + d] = a[jt];
    }
}

// ---------------------------------------------------------------------------
// K6b: merge the 16 chunk partials per (b,h,u); write selected row (over fill).
// ---------------------------------------------------------------------------
__global__ void k_attn_merge(float* __restrict__ out) {
    int u  = blockIdx.x % UU;
    int bh = blockIdx.x / UU;
    int b = bh >> 3, h = bh & 7;
    int d = threadIdx.x;
    int base = (bh * UU + u) * NCH;
    float gm = -CUDART_INF_F;
#pragma unroll
    for (int c = 0; c < NCH; c++) gm = fmaxf(gm, g_pm[base + c]);
    float tot = 0.f, val = 0.f;
#pragma unroll
    for (int c = 0; c < NCH; c++) {
        float e = expf(g_pm[base + c] - gm);
        tot += g_ps[base + c] * e;
        val += g_pa[(base + c) * DD + d] * e;
    }
    int lq = g_Mtop[bh * UU + u];
    out[(((size_t)(b * LL + lq)) * HH + h) * DD + d] = val / tot;
}

// ---------------------------------------------------------------------------
extern "C" void kernel_launch(void* const* d_in, const int* in_sizes, int n_in,
                              void* d_out, int out_size) {
    const float* Q = (const float*)d_in[0];
    const float* K = (const float*)d_in[1];
    const float* V = (const float*)d_in[2];
    float* out = (float*)d_out;

    cudaFuncSetAttribute(k_attn_part, cudaFuncAttributeMaxDynamicSharedMemorySize,
                         SH_BYTES);

    k_rng<<<(NEL + 255) / 256, 256>>>();
    k_sampleM<<<(BH * LL) / 8, 256>>>(Q, K);
    k_topk<<<BH, 256>>>();
    k_vmean<<<BH, 256>>>(V);
    k_fill<<<(BB * LL * HH * (DD / 4)) / 256, 256>>>(out);
    k_attn_part<<<BH * NCH, 256, SH_BYTES>>>(Q, K, V);
    k_attn_merge<<<BH * UU, DD>>>(out);
}

// round 4
// speedup vs baseline: 1.2124x; 1.2124x over previous
#include <cuda_runtime.h>
#include <stdint.h>
#include <math_constants.h>

// ProbSparse attention (Informer) — B=4, L=2048, H=8, D=64, U_part=u=40.
// Layout of all tensors: (B, L, H, D) row-major.

#define BB 4
#define LL 2048
#define HH 8
#define DD 64
#define UU 40            // top-u queries
#define SS 40            // samples per query
#define BH (BB*HH)       // 32
#define NEL (LL*SS)      // 81920 sampled indices
#define NCH 16           // key chunks for split-K attention
#define CH  128          // keys per chunk
#define SCALE 0.125f     // 1/sqrt(64)

__device__ __align__(16) int   g_idx[NEL];
__device__ __align__(16) float g_M[BH*LL];
__device__ __align__(16) int   g_Mtop[BH*UU];
__device__ __align__(16) float g_Vmean[BH*DD];
__device__ __align__(16) float g_pm[BH*UU*NCH];
__device__ __align__(16) float g_ps[BH*UU*NCH];
__device__ __align__(16) float g_pa[BH*UU*NCH*DD];

// ---------------------------------------------------------------------------
// Threefry-2x32-20, constexpr-evaluable.
// ---------------------------------------------------------------------------
__host__ __device__ constexpr uint64_t tf2x32(uint32_t k0, uint32_t k1,
                                              uint32_t c0, uint32_t c1) {
    uint32_t ks0 = k0, ks1 = k1, ks2 = k0 ^ k1 ^ 0x1BD11BDAu;
    uint32_t x0 = c0 + ks0, x1 = c1 + ks1;
    const int rotA[4] = {13, 15, 26, 6};
    const int rotB[4] = {17, 29, 16, 24};
    for (int g = 0; g < 5; g++) {
        const int* rot = (g & 1) ? rotB : rotA;
        for (int r = 0; r < 4; r++) {
            x0 += x1;
            x1 = (x1 << rot[r]) | (x1 >> (32 - rot[r]));
            x1 ^= x0;
        }
        uint32_t inj0 = 0, inj1 = 0;
        switch (g) {
            case 0: inj0 = ks1; inj1 = ks2 + 1u; break;
            case 1: inj0 = ks2; inj1 = ks0 + 2u; break;
            case 2: inj0 = ks0; inj1 = ks1 + 3u; break;
            case 3: inj0 = ks1; inj1 = ks2 + 4u; break;
            case 4: inj0 = ks2; inj1 = ks0 + 5u; break;
        }
        x0 += inj0; x1 += inj1;
    }
    return ((uint64_t)x0 << 32) | (uint64_t)x1;
}

// k2 = second output key of jax.random.split(key(42), 2) (partitionable mode).
constexpr uint64_t K2PAIR = tf2x32(0u, 42u, 0u, 1u);
#define K2_HI ((uint32_t)(K2PAIR >> 32))
#define K2_LO ((uint32_t)(K2PAIR & 0xffffffffu))

// ---------------------------------------------------------------------------
// K1: indices = fold-xor threefry stream under split key, & 2047.
// Also zeroes g_Vmean for this launch (k_vmean accumulates atomically).
// ---------------------------------------------------------------------------
__global__ void k_rng() {
    int i = blockIdx.x * blockDim.x + threadIdx.x;
    if (i < BH * DD) g_Vmean[i] = 0.f;
    if (i >= NEL) return;
    uint64_t y = tf2x32(K2_HI, K2_LO, 0u, (uint32_t)i);
    uint32_t bits = (uint32_t)(y >> 32) ^ (uint32_t)(y & 0xffffffffu);
    g_idx[i] = (int)(bits & (LL - 1));
}

// ---------------------------------------------------------------------------
// K2: M[b,h,l] = max_s(q·k_sample) - sum_s(q·k_sample)/L.  One warp per (b,h,l).
// float2 per lane: one 8B load per sampled row per lane.
// ---------------------------------------------------------------------------
__global__ void k_sampleM(const float* __restrict__ Q, const float* __restrict__ K) {
    int wg   = (blockIdx.x * blockDim.x + threadIdx.x) >> 5;
    int lane = threadIdx.x & 31;
    if (wg >= BH * LL) return;
    int l  = wg & (LL - 1);
    int bh = wg >> 11;
    int h  = bh & (HH - 1);
    int b  = bh >> 3;

    const float2* qp = (const float2*)(Q + (((size_t)(b * LL + l)) * HH + h) * DD);
    float2 q = qp[lane];

    float mx = -CUDART_INF_F, sm = 0.f;
    const int* idx = g_idx + l * SS;
#pragma unroll 8
    for (int s = 0; s < SS; s++) {
        int kk = idx[s];
        const float2* kp = (const float2*)(K + (((size_t)(b * LL + kk)) * HH + h) * DD);
        float2 kv = kp[lane];
        float p = q.x * kv.x + q.y * kv.y;
        p += __shfl_xor_sync(0xffffffffu, p, 16);
        p += __shfl_xor_sync(0xffffffffu, p, 8);
        p += __shfl_xor_sync(0xffffffffu, p, 4);
        p += __shfl_xor_sync(0xffffffffu, p, 2);
        p += __shfl_xor_sync(0xffffffffu, p, 1);
        mx = fmaxf(mx, p);
        sm += p;
    }
    if (lane == 0) g_M[wg] = mx - sm * (1.0f / (float)LL);
}

// ---------------------------------------------------------------------------
// K3: exact top-40 per (b,h) via in-smem bitonic sort of (value, index) with
// comparator: v desc, index asc (matches jax.lax.top_k). 512 threads.
// ---------------------------------------------------------------------------
__global__ void k_topk() {
    int bh = blockIdx.x;
    __shared__ float sv[LL];
    __shared__ int   si[LL];
    int t = threadIdx.x;
    for (int i = t; i < LL; i += 512) { sv[i] = g_M[bh * LL + i]; si[i] = i; }
    __syncthreads();
    for (int k = 2; k <= LL; k <<= 1) {
        for (int j = k >> 1; j > 0; j >>= 1) {
            for (int i = t; i < LL; i += 512) {
                int p = i ^ j;
                if (p > i) {
                    bool asc = (i & k) == 0;
                    float va = sv[i], vp = sv[p];
                    int   ia = si[i], ip = si[p];
                    // does p's element precede i's in (v desc, idx asc) order?
                    bool pre = (vp > va) || (vp == va && ip < ia);
                    if (asc == pre) {
                        sv[i] = vp; sv[p] = va;
                        si[i] = ip; si[p] = ia;
                    }
                }
            }
            __syncthreads();
        }
    }
    if (t < UU) g_Mtop[bh * UU + t] = si[t];
}

// ---------------------------------------------------------------------------
// K4: V_mean partials; 512 blocks (bh x 16 L-chunks), atomicAdd merge.
// ---------------------------------------------------------------------------
__global__ void k_vmean(const float* __restrict__ V) {
    int blk = blockIdx.x;
    int bh = blk >> 4, chn = blk & 15;
    int b = bh >> 3, h = bh & 7;
    int t = threadIdx.x;
    int d = t & 63, sub = t >> 6;            // 4 subgroups of 32 rows each
    float s = 0.f;
#pragma unroll 8
    for (int i = 0; i < 32; i++) {
        int l = chn * 128 + sub + i * 4;
        s += V[(((size_t)(b * LL + l)) * HH + h) * DD + d];
    }
    __shared__ float red[256];
    red[t] = s;
    __syncthreads();
    if (t < 64) {
        float tot = red[t] + red[t + 64] + red[t + 128] + red[t + 192];
        atomicAdd(&g_Vmean[bh * DD + t], tot * (1.0f / (float)LL));
    }
}

// ---------------------------------------------------------------------------
// K5: out[b,l,h,:] = V_mean[b,h,:] for all l.
// ---------------------------------------------------------------------------
__global__ void k_fill(float* __restrict__ out) {
    int i = blockIdx.x * blockDim.x + threadIdx.x;
    if (i >= BB * LL * HH * (DD / 4)) return;
    int q4  = i & 15;
    int row = i >> 4;
    int h = row & 7;
    int b = row >> 14;
    float4 vm = reinterpret_cast<const float4*>(g_Vmean)[((b << 3) + h) * (DD / 4) + q4];
    reinterpret_cast<float4*>(out)[i] = vm;
}

// ---------------------------------------------------------------------------
// K6a: split-K attention partials. Block = (b,h, key-chunk of 128), 256 thr.
// ---------------------------------------------------------------------------
#define QS_PITCH 65
#define KS_PITCH 65
#define S_PITCH  129
#define SH_FLOATS (UU*QS_PITCH + CH*KS_PITCH + CH*KS_PITCH + UU*S_PITCH)
#define SH_BYTES  (SH_FLOATS*4 + UU*4)

__global__ void k_attn_part(const float* __restrict__ Q, const float* __restrict__ K,
                            const float* __restrict__ V) {
    int ch = blockIdx.x & (NCH - 1);
    int bh = blockIdx.x >> 4;
    int b = bh >> 3, h = bh & 7;
    int t = threadIdx.x;

    extern __shared__ float sh[];
    float* Qs = sh;                          // [40][65]
    float* Ks = Qs + UU * QS_PITCH;          // [128][65]
    float* Vs = Ks + CH * KS_PITCH;          // [128][65]
    float* S  = Vs + CH * KS_PITCH;          // [40][129]
    int* sidx = (int*)(S + UU * S_PITCH);    // [40]

    if (t < UU) sidx[t] = g_Mtop[bh * UU + t];
    __syncthreads();

    for (int i = t; i < UU * (DD / 4); i += 256) {
        int j = i >> 4, q4 = i & 15;
        float4 v = *(const float4*)(Q + (((size_t)(b * LL + sidx[j])) * HH + h) * DD + q4 * 4);
        float* dst = Qs + j * QS_PITCH + q4 * 4;
        dst[0] = v.x; dst[1] = v.y; dst[2] = v.z; dst[3] = v.w;
    }
    int k0 = ch * CH;
    for (int i = t; i < CH * (DD / 4); i += 256) {
        int r = i >> 4, q4 = i & 15;
        size_t base = (((size_t)(b * LL + k0 + r)) * HH + h) * DD + q4 * 4;
        float4 kv = *(const float4*)(K + base);
        float4 vv = *(const float4*)(V + base);
        float* dk = Ks + r * KS_PITCH + q4 * 4;
        float* dv = Vs + r * KS_PITCH + q4 * 4;
        dk[0] = kv.x; dk[1] = kv.y; dk[2] = kv.z; dk[3] = kv.w;
        dv[0] = vv.x; dv[1] = vv.y; dv[2] = vv.z; dv[3] = vv.w;
    }
    __syncthreads();

    // ---- phase 1: S[j][k] = scale * dot(Qs[j], Ks[k]) ----
    {
        int kg = t & 31, jg = t >> 5;
        float acc[5][4];
#pragma unroll
        for (int jt = 0; jt < 5; jt++)
#pragma unroll
            for (int kt = 0; kt < 4; kt++) acc[jt][kt] = 0.f;
#pragma unroll 8
        for (int d = 0; d < DD; d++) {
            float qv[5], kv[4];
#pragma unroll
            for (int jt = 0; jt < 5; jt++) qv[jt] = Qs[(jg + 8 * jt) * QS_PITCH + d];
#pragma unroll
            for (int kt = 0; kt < 4; kt++) kv[kt] = Ks[(kg + 32 * kt) * KS_PITCH + d];
#pragma unroll
            for (int jt = 0; jt < 5; jt++)
#pragma unroll
                for (int kt = 0; kt < 4; kt++) acc[jt][kt] += qv[jt] * kv[kt];
        }
#pragma unroll
        for (int jt = 0; jt < 5; jt++)
#pragma unroll
            for (int kt = 0; kt < 4; kt++)
                S[(jg + 8 * jt) * S_PITCH + (kg + 32 * kt)] = acc[jt][kt] * SCALE;
    }
    __syncthreads();

    // ---- phase 2: per-row chunk softmax stats; S <- exp(S - m) ----
    {
        int lane = t & 31, w = t >> 5;
#pragma unroll
        for (int i = 0; i < 5; i++) {
            int j = w * 5 + i;
            float* row = S + j * S_PITCH;
            float v0 = row[lane], v1 = row[lane + 32], v2 = row[lane + 64], v3 = row[lane + 96];
            float m = fmaxf(fmaxf(v0, v1), fmaxf(v2, v3));
            for (int off = 16; off; off >>= 1) m = fmaxf(m, __shfl_xor_sync(0xffffffffu, m, off));
            float e0 = expf(v0 - m), e1 = expf(v1 - m), e2 = expf(v2 - m), e3 = expf(v3 - m);
            row[lane] = e0; row[lane + 32] = e1; row[lane + 64] = e2; row[lane + 96] = e3;
            float s = e0 + e1 + e2 + e3;
            for (int off = 16; off; off >>= 1) s += __shfl_xor_sync(0xffffffffu, s, off);
            if (lane == 0) {
                g_pm[(bh * UU + j) * NCH + ch] = m;
                g_ps[(bh * UU + j) * NCH + ch] = s;
            }
        }
    }
    __syncthreads();

    // ---- phase 3: partial a[j][d] = sum_k exp * Vs[k][d] ----
    {
        int d = t & 63, grp = t >> 6;
        float a[10];
#pragma unroll
        for (int jt = 0; jt < 10; jt++) a[jt] = 0.f;
#pragma unroll 4
        for (int k = 0; k < CH; k++) {
            float vv = Vs[k * KS_PITCH + d];
#pragma unroll
            for (int jt = 0; jt < 10; jt++) a[jt] += S[(grp * 10 + jt) * S_PITCH + k] * vv;
        }
#pragma unroll
        for (int jt = 0; jt < 10; jt++)
            g_pa[((bh * UU + grp * 10 + jt) * NCH + ch) * DD + d] = a[jt];
    }
}

// ---------------------------------------------------------------------------
// K6b: merge the 16 chunk partials per (b,h,u); write selected row (over fill).
// ---------------------------------------------------------------------------
__global__ void k_attn_merge(float* __restrict__ out) {
    int u  = blockIdx.x % UU;
    int bh = blockIdx.x / UU;
    int b = bh >> 3, h = bh & 7;
    int d = threadIdx.x;
    int base = (bh * UU + u) * NCH;
    float gm = -CUDART_INF_F;
#pragma unroll
    for (int c = 0; c < NCH; c++) gm = fmaxf(gm, g_pm[base + c]);
    float tot = 0.f, val = 0.f;
#pragma unroll
    for (int c = 0; c < NCH; c++) {
        float e = expf(g_pm[base + c] - gm);
        tot += g_ps[base + c] * e;
        val += g_pa[(base + c) * DD + d] * e;
    }
    int lq = g_Mtop[bh * UU + u];
    out[(((size_t)(b * LL + lq)) * HH + h) * DD + d] = val / tot;
}

// ---------------------------------------------------------------------------
extern "C" void kernel_launch(void* const* d_in, const int* in_sizes, int n_in,
                              void* d_out, int out_size) {
    const float* Q = (const float*)d_in[0];
    const float* K = (const float*)d_in[1];
    const float* V = (const float*)d_in[2];
    float* out = (float*)d_out;

    cudaFuncSetAttribute(k_attn_part, cudaFuncAttributeMaxDynamicSharedMemorySize,
                         SH_BYTES);

    k_rng<<<(NEL + 255) / 256, 256>>>();
    k_sampleM<<<(BH * LL) / 8, 256>>>(Q, K);
    k_topk<<<BH, 512>>>();
    k_vmean<<<BH * 16, 256>>>(V);
    k_fill<<<(BB * LL * HH * (DD / 4)) / 256, 256>>>(out);
    k_attn_part<<<BH * NCH, 256, SH_BYTES>>>(Q, K, V);
    k_attn_merge<<<BH * UU, DD>>>(out);
}